// round 4
// baseline (speedup 1.0000x reference)
#include <cuda_runtime.h>
#include <cuda_bf16.h>

#define N_GRID 64
#define N1 65
#define W_FEAT 256
#define NBUCKETS 32768          // (ix<<9)|(iy<<3)|(iz>>3)
#define B_MAX 262144

// Scratch (allocation-free rule: __device__ globals).
// g_hist must be zero at first use; static init gives that, and scan_kernel
// resets it to zero each pass so graph replays stay correct.
__device__ int g_hist[NBUCKETS];      // zero-initialized
__device__ int g_offsets[NBUCKETS];
__device__ int g_cell[B_MAX];
__device__ int g_perm[B_MAX];

__device__ __forceinline__ int point_bucket(const float* __restrict__ x, int p) {
    const float scale = (float)N_GRID / 2.0f;
    float rx = (x[p * 3 + 0] + 1.0f) * scale;
    float ry = (x[p * 3 + 1] + 1.0f) * scale;
    float rz = (x[p * 3 + 2] + 1.0f) * scale;
    int ix = min(max((int)floorf(rx), 0), N_GRID - 1);
    int iy = min(max((int)floorf(ry), 0), N_GRID - 1);
    int iz = min(max((int)floorf(rz), 0), N_GRID - 1);
    return (ix << 9) | (iy << 3) | (iz >> 3);
}

__global__ void hist_kernel(const float* __restrict__ x, int B) {
    int p = blockIdx.x * blockDim.x + threadIdx.x;
    if (p >= B) return;
    int b = point_bucket(x, p);
    g_cell[p] = b;
    atomicAdd(&g_hist[b], 1);
}

// One block, 1024 threads, 32 buckets each: exclusive scan of g_hist into
// g_offsets, then reset g_hist to zero for the next replay.
__global__ void __launch_bounds__(1024) scan_kernel() {
    __shared__ int s[1024];
    int tid = threadIdx.x;
    int base = tid * 32;

    int local[32];
    int sum = 0;
    #pragma unroll
    for (int i = 0; i < 32; i++) {
        local[i] = g_hist[base + i];
        sum += local[i];
    }
    s[tid] = sum;
    __syncthreads();
    #pragma unroll
    for (int off = 1; off < 1024; off <<= 1) {
        int t = (tid >= off) ? s[tid - off] : 0;
        __syncthreads();
        s[tid] += t;
        __syncthreads();
    }
    int run = s[tid] - sum;   // exclusive prefix of this thread's chunk
    #pragma unroll
    for (int i = 0; i < 32; i++) {
        g_offsets[base + i] = run;
        run += local[i];
        g_hist[base + i] = 0;   // ready for next replay
    }
}

__global__ void scatter_kernel(int B) {
    int p = blockIdx.x * blockDim.x + threadIdx.x;
    if (p >= B) return;
    int pos = atomicAdd(&g_offsets[g_cell[p]], 1);
    g_perm[pos] = p;
}

// warp-per-point trilinear gather; warps walk points in bucket-sorted order.
__global__ void __launch_bounds__(256) trilerp_kernel(
    const float* __restrict__ x,
    const float* __restrict__ grid_value,
    const float* __restrict__ grid_feature,
    float* __restrict__ out_val,
    float* __restrict__ out_feat,
    int B)
{
    int warp_id = (blockIdx.x * blockDim.x + threadIdx.x) >> 5;
    int lane = threadIdx.x & 31;
    if (warp_id >= B) return;

    int p = g_perm[warp_id];

    float px = x[p * 3 + 0];
    float py = x[p * 3 + 1];
    float pz = x[p * 3 + 2];

    const float scale = (float)N_GRID / 2.0f;
    float rx = (px + 1.0f) * scale;
    float ry = (py + 1.0f) * scale;
    float rz = (pz + 1.0f) * scale;

    bool valid = (rx >= 0.0f) && (rx <= (float)N_GRID) &&
                 (ry >= 0.0f) && (ry <= (float)N_GRID) &&
                 (rz >= 0.0f) && (rz <= (float)N_GRID);

    int ix = min(max((int)floorf(rx), 0), N_GRID - 1);
    int iy = min(max((int)floorf(ry), 0), N_GRID - 1);
    int iz = min(max((int)floorf(rz), 0), N_GRID - 1);

    float tx = rx - (float)ix;
    float ty = ry - (float)iy;
    float tz = rz - (float)iz;

    int base = (ix * N1 + iy) * N1 + iz;

    float wx0 = 1.0f - tx, wx1 = tx;
    float wy0 = 1.0f - ty, wy1 = ty;
    float wz0 = 1.0f - tz, wz1 = tz;

    int   flat[8];
    float w[8];
    flat[0] = base;                      w[0] = wx0 * wy0 * wz0;
    flat[1] = base + 1;                  w[1] = wx0 * wy0 * wz1;
    flat[2] = base + N1;                 w[2] = wx0 * wy1 * wz0;
    flat[3] = base + N1 + 1;             w[3] = wx0 * wy1 * wz1;
    flat[4] = base + N1 * N1;            w[4] = wx1 * wy0 * wz0;
    flat[5] = base + N1 * N1 + 1;        w[5] = wx1 * wy0 * wz1;
    flat[6] = base + N1 * N1 + N1;       w[6] = wx1 * wy1 * wz0;
    flat[7] = base + N1 * N1 + N1 + 1;   w[7] = wx1 * wy1 * wz1;

    float4 acc0 = make_float4(0.f, 0.f, 0.f, 0.f);
    float4 acc1 = make_float4(0.f, 0.f, 0.f, 0.f);

    #pragma unroll
    for (int c = 0; c < 8; c++) {
        const float4* row = (const float4*)(grid_feature + (size_t)flat[c] * W_FEAT);
        float4 f0 = __ldg(&row[lane]);
        float4 f1 = __ldg(&row[lane + 32]);
        float wc = w[c];
        acc0.x += wc * f0.x; acc0.y += wc * f0.y;
        acc0.z += wc * f0.z; acc0.w += wc * f0.w;
        acc1.x += wc * f1.x; acc1.y += wc * f1.y;
        acc1.z += wc * f1.z; acc1.w += wc * f1.w;
    }

    if (!valid) {
        acc0 = make_float4(0.f, 0.f, 0.f, 0.f);
        acc1 = make_float4(0.f, 0.f, 0.f, 0.f);
    }

    float4* fo = (float4*)(out_feat + (size_t)p * W_FEAT);
    fo[lane]      = acc0;
    fo[lane + 32] = acc1;

    if (lane == 0) {
        float s = 0.0f;
        #pragma unroll
        for (int c = 0; c < 8; c++) s += w[c] * __ldg(&grid_value[flat[c]]);
        out_val[p] = valid ? s : 0.0f;
    }
}

extern "C" void kernel_launch(void* const* d_in, const int* in_sizes, int n_in,
                              void* d_out, int out_size) {
    const float* x            = (const float*)d_in[0];
    const float* grid_value   = (const float*)d_in[1];
    const float* grid_feature = (const float*)d_in[2];

    int B = in_sizes[0] / 3;

    float* out_val  = (float*)d_out;        // (B, 1)
    float* out_feat = out_val + B;          // (B, 256)

    // --- bucket sort by coarse cell key (4 launches total incl. main) ---
    hist_kernel<<<(B + 255) / 256, 256>>>(x, B);
    scan_kernel<<<1, 1024>>>();
    scatter_kernel<<<(B + 255) / 256, 256>>>(B);

    int warps_per_block = 8;                 // 256 threads
    int blocks = (B + warps_per_block - 1) / warps_per_block;
    trilerp_kernel<<<blocks, 256>>>(x, grid_value, grid_feature,
                                    out_val, out_feat, B);
}

// round 5
// speedup vs baseline: 1.0146x; 1.0146x over previous
#include <cuda_runtime.h>
#include <cuda_bf16.h>

#define N_GRID 64
#define N1 65
#define W_FEAT 256
#define NCELLS (N_GRID * N_GRID * N_GRID)   // 262144
#define B_MAX 262144

// Scratch (allocation-free rule: __device__ globals).
// g_hist must be zero at first use: static zero-init gives that, and
// scan_block_kernel resets it each pass so graph replays stay correct.
__device__ int g_hist[NCELLS];        // zero-initialized
__device__ int g_offsets[NCELLS];     // exclusive prefix within 1024-chunk
__device__ int g_blocksums[256];
__device__ int g_cell[B_MAX];
__device__ int g_perm[B_MAX];

__global__ void hist_kernel(const float* __restrict__ x, int B) {
    int p = blockIdx.x * blockDim.x + threadIdx.x;
    if (p >= B) return;
    const float scale = (float)N_GRID / 2.0f;
    float rx = (x[p * 3 + 0] + 1.0f) * scale;
    float ry = (x[p * 3 + 1] + 1.0f) * scale;
    float rz = (x[p * 3 + 2] + 1.0f) * scale;
    int ix = min(max((int)floorf(rx), 0), N_GRID - 1);
    int iy = min(max((int)floorf(ry), 0), N_GRID - 1);
    int iz = min(max((int)floorf(rz), 0), N_GRID - 1);
    int cell = (ix * N_GRID + iy) * N_GRID + iz;   // lexicographic = memory order
    g_cell[p] = cell;
    atomicAdd(&g_hist[cell], 1);
}

// 256 blocks x 1024 threads. Per-chunk exclusive scan into g_offsets,
// reset g_hist to 0, emit chunk total.
__global__ void __launch_bounds__(1024) scan_block_kernel() {
    __shared__ int s[1024];
    int tid = threadIdx.x;
    int i = blockIdx.x * 1024 + tid;
    int v = g_hist[i];
    s[tid] = v;
    __syncthreads();
    #pragma unroll
    for (int off = 1; off < 1024; off <<= 1) {
        int t = (tid >= off) ? s[tid - off] : 0;
        __syncthreads();
        s[tid] += t;
        __syncthreads();
    }
    g_offsets[i] = s[tid] - v;        // exclusive within chunk
    g_hist[i] = 0;                    // ready for next replay
    if (tid == 1023) g_blocksums[blockIdx.x] = s[1023];
}

// 1 block x 256 threads: exclusive scan of chunk sums in place.
__global__ void scan_top_kernel() {
    __shared__ int s[256];
    int tid = threadIdx.x;
    int v = g_blocksums[tid];
    s[tid] = v;
    __syncthreads();
    #pragma unroll
    for (int off = 1; off < 256; off <<= 1) {
        int t = (tid >= off) ? s[tid - off] : 0;
        __syncthreads();
        s[tid] += t;
        __syncthreads();
    }
    g_blocksums[tid] = s[tid] - v;
}

__global__ void scatter_kernel(int B) {
    int p = blockIdx.x * blockDim.x + threadIdx.x;
    if (p >= B) return;
    int c = g_cell[p];
    int pos = atomicAdd(&g_offsets[c], 1) + g_blocksums[c >> 10];
    g_perm[pos] = p;
}

// 2 warps per point; each warp covers 128 of 256 features (1 float4/lane).
// All 8 corner feature rows addressed as [base + compile-time-imm].
__global__ void __launch_bounds__(256) trilerp_kernel(
    const float* __restrict__ x,
    const float* __restrict__ grid_value,
    const float* __restrict__ grid_feature,
    float* __restrict__ out_val,
    float* __restrict__ out_feat,
    int B)
{
    int gw = (blockIdx.x * blockDim.x + threadIdx.x) >> 5;  // global warp
    int lane = threadIdx.x & 31;
    int point = gw >> 1;
    int half = gw & 1;
    if (point >= B) return;

    int p = g_perm[point];

    float px = x[p * 3 + 0];
    float py = x[p * 3 + 1];
    float pz = x[p * 3 + 2];

    const float scale = (float)N_GRID / 2.0f;
    float rx = (px + 1.0f) * scale;
    float ry = (py + 1.0f) * scale;
    float rz = (pz + 1.0f) * scale;

    bool valid = (rx >= 0.0f) && (rx <= (float)N_GRID) &&
                 (ry >= 0.0f) && (ry <= (float)N_GRID) &&
                 (rz >= 0.0f) && (rz <= (float)N_GRID);

    int ix = min(max((int)floorf(rx), 0), N_GRID - 1);
    int iy = min(max((int)floorf(ry), 0), N_GRID - 1);
    int iz = min(max((int)floorf(rz), 0), N_GRID - 1);

    float tx = rx - (float)ix;
    float ty = ry - (float)iy;
    float tz = rz - (float)iz;

    int base = (ix * N1 + iy) * N1 + iz;

    float wx0 = 1.0f - tx, wx1 = tx;
    float wy0 = 1.0f - ty, wy1 = ty;
    float wz0 = 1.0f - tz, wz1 = tz;

    float w[8];
    w[0] = wx0 * wy0 * wz0;
    w[1] = wx0 * wy0 * wz1;
    w[2] = wx0 * wy1 * wz0;
    w[3] = wx0 * wy1 * wz1;
    w[4] = wx1 * wy0 * wz0;
    w[5] = wx1 * wy0 * wz1;
    w[6] = wx1 * wy1 * wz0;
    w[7] = wx1 * wy1 * wz1;

    // Compile-time element offsets of the 8 corners (units: floats).
    // Loads become LDG [Rbase + imm]; max imm = 4290*256*4B = 4.4MB < 8MB range.
    const float* bp = grid_feature + (size_t)base * W_FEAT + half * 128 + lane * 4;

    float4 acc = make_float4(0.f, 0.f, 0.f, 0.f);

    // Two batches of 4 corners in flight (MLP=4, 16 data regs).
    #pragma unroll
    for (int b = 0; b < 2; b++) {
        float4 f[4];
        #pragma unroll
        for (int j = 0; j < 4; j++) {
            int c = b * 4 + j;
            int off = (((c >> 2) & 1) * (N1 * N1) + ((c >> 1) & 1) * N1 + (c & 1)) * W_FEAT;
            f[j] = __ldg((const float4*)(bp + off));
        }
        #pragma unroll
        for (int j = 0; j < 4; j++) {
            float wc = w[b * 4 + j];
            acc.x += wc * f[j].x; acc.y += wc * f[j].y;
            acc.z += wc * f[j].z; acc.w += wc * f[j].w;
        }
    }

    if (!valid) acc = make_float4(0.f, 0.f, 0.f, 0.f);

    *(float4*)(out_feat + (size_t)p * W_FEAT + half * 128 + lane * 4) = acc;

    // Scalar grid_value: 8 lanes load+weight one corner each, shfl-reduce.
    if (half == 0) {
        float s = 0.0f;
        if (lane < 8) {
            int off = ((lane >> 2) & 1) * (N1 * N1) + ((lane >> 1) & 1) * N1 + (lane & 1);
            s = w[lane] * __ldg(grid_value + base + off);
        }
        s += __shfl_xor_sync(0xFFFFFFFF, s, 1);
        s += __shfl_xor_sync(0xFFFFFFFF, s, 2);
        s += __shfl_xor_sync(0xFFFFFFFF, s, 4);
        if (lane == 0) out_val[p] = valid ? s : 0.0f;
    }
}

extern "C" void kernel_launch(void* const* d_in, const int* in_sizes, int n_in,
                              void* d_out, int out_size) {
    const float* x            = (const float*)d_in[0];
    const float* grid_value   = (const float*)d_in[1];
    const float* grid_feature = (const float*)d_in[2];

    int B = in_sizes[0] / 3;

    float* out_val  = (float*)d_out;        // (B, 1)
    float* out_feat = out_val + B;          // (B, 256)

    // --- counting sort by full cell id (lean 4-kernel pipeline) ---
    hist_kernel<<<(B + 255) / 256, 256>>>(x, B);
    scan_block_kernel<<<NCELLS / 1024, 1024>>>();
    scan_top_kernel<<<1, 256>>>();
    scatter_kernel<<<(B + 255) / 256, 256>>>(B);

    // --- main gather: 2 warps per point ---
    long long total_warps = 2LL * B;
    int blocks = (int)((total_warps * 32 + 255) / 256);
    trilerp_kernel<<<blocks, 256>>>(x, grid_value, grid_feature,
                                    out_val, out_feat, B);
}

// round 6
// speedup vs baseline: 1.3233x; 1.3042x over previous
#include <cuda_runtime.h>
#include <cuda_bf16.h>

#define N_GRID 64
#define N1 65
#define W_FEAT 256
#define NCELLS (N_GRID * N_GRID * N_GRID)   // 262144
#define B_MAX 262144

// Scratch (allocation-free rule: __device__ globals).
// g_hist must be zero at first use: static zero-init gives that, and
// scan_block_kernel resets it each pass so graph replays stay correct.
__device__ int g_hist[NCELLS];        // zero-initialized
__device__ int g_offsets[NCELLS];     // exclusive prefix within 1024-chunk
__device__ int g_blocksums[256];
__device__ int g_cell[B_MAX];
__device__ int g_perm[B_MAX];

__global__ void hist_kernel(const float* __restrict__ x, int B) {
    int p = blockIdx.x * blockDim.x + threadIdx.x;
    if (p >= B) return;
    const float scale = (float)N_GRID / 2.0f;
    float rx = (x[p * 3 + 0] + 1.0f) * scale;
    float ry = (x[p * 3 + 1] + 1.0f) * scale;
    float rz = (x[p * 3 + 2] + 1.0f) * scale;
    int ix = min(max((int)floorf(rx), 0), N_GRID - 1);
    int iy = min(max((int)floorf(ry), 0), N_GRID - 1);
    int iz = min(max((int)floorf(rz), 0), N_GRID - 1);
    int cell = (ix * N_GRID + iy) * N_GRID + iz;   // lexicographic = memory order
    g_cell[p] = cell;
    atomicAdd(&g_hist[cell], 1);
}

// 256 blocks x 1024 threads. Per-chunk exclusive scan into g_offsets,
// reset g_hist to 0, emit chunk total.
__global__ void __launch_bounds__(1024) scan_block_kernel() {
    __shared__ int s[1024];
    int tid = threadIdx.x;
    int i = blockIdx.x * 1024 + tid;
    int v = g_hist[i];
    s[tid] = v;
    __syncthreads();
    #pragma unroll
    for (int off = 1; off < 1024; off <<= 1) {
        int t = (tid >= off) ? s[tid - off] : 0;
        __syncthreads();
        s[tid] += t;
        __syncthreads();
    }
    g_offsets[i] = s[tid] - v;        // exclusive within chunk
    g_hist[i] = 0;                    // ready for next replay
    if (tid == 1023) g_blocksums[blockIdx.x] = s[1023];
}

// 1 block x 256 threads: exclusive scan of chunk sums in place.
__global__ void scan_top_kernel() {
    __shared__ int s[256];
    int tid = threadIdx.x;
    int v = g_blocksums[tid];
    s[tid] = v;
    __syncthreads();
    #pragma unroll
    for (int off = 1; off < 256; off <<= 1) {
        int t = (tid >= off) ? s[tid - off] : 0;
        __syncthreads();
        s[tid] += t;
        __syncthreads();
    }
    g_blocksums[tid] = s[tid] - v;
}

__global__ void scatter_kernel(int B) {
    int p = blockIdx.x * blockDim.x + threadIdx.x;
    if (p >= B) return;
    int c = g_cell[p];
    int pos = atomicAdd(&g_offsets[c], 1) + g_blocksums[c >> 10];
    g_perm[pos] = p;
}

// warp-per-point trilinear gather; warps walk points in cell-sorted order.
// (R2-measured-best structure: 16 float4 loads in flight per warp.)
__global__ void __launch_bounds__(256) trilerp_kernel(
    const float* __restrict__ x,
    const float* __restrict__ grid_value,
    const float* __restrict__ grid_feature,
    float* __restrict__ out_val,
    float* __restrict__ out_feat,
    int B)
{
    int warp_id = (blockIdx.x * blockDim.x + threadIdx.x) >> 5;
    int lane = threadIdx.x & 31;
    if (warp_id >= B) return;

    int p = g_perm[warp_id];

    float px = x[p * 3 + 0];
    float py = x[p * 3 + 1];
    float pz = x[p * 3 + 2];

    const float scale = (float)N_GRID / 2.0f;
    float rx = (px + 1.0f) * scale;
    float ry = (py + 1.0f) * scale;
    float rz = (pz + 1.0f) * scale;

    bool valid = (rx >= 0.0f) && (rx <= (float)N_GRID) &&
                 (ry >= 0.0f) && (ry <= (float)N_GRID) &&
                 (rz >= 0.0f) && (rz <= (float)N_GRID);

    int ix = min(max((int)floorf(rx), 0), N_GRID - 1);
    int iy = min(max((int)floorf(ry), 0), N_GRID - 1);
    int iz = min(max((int)floorf(rz), 0), N_GRID - 1);

    float tx = rx - (float)ix;
    float ty = ry - (float)iy;
    float tz = rz - (float)iz;

    int base = (ix * N1 + iy) * N1 + iz;

    float wx0 = 1.0f - tx, wx1 = tx;
    float wy0 = 1.0f - ty, wy1 = ty;
    float wz0 = 1.0f - tz, wz1 = tz;

    int   flat[8];
    float w[8];
    flat[0] = base;                      w[0] = wx0 * wy0 * wz0;
    flat[1] = base + 1;                  w[1] = wx0 * wy0 * wz1;
    flat[2] = base + N1;                 w[2] = wx0 * wy1 * wz0;
    flat[3] = base + N1 + 1;             w[3] = wx0 * wy1 * wz1;
    flat[4] = base + N1 * N1;            w[4] = wx1 * wy0 * wz0;
    flat[5] = base + N1 * N1 + 1;        w[5] = wx1 * wy0 * wz1;
    flat[6] = base + N1 * N1 + N1;       w[6] = wx1 * wy1 * wz0;
    flat[7] = base + N1 * N1 + N1 + 1;   w[7] = wx1 * wy1 * wz1;

    float4 acc0 = make_float4(0.f, 0.f, 0.f, 0.f);
    float4 acc1 = make_float4(0.f, 0.f, 0.f, 0.f);

    #pragma unroll
    for (int c = 0; c < 8; c++) {
        const float4* row = (const float4*)(grid_feature + (size_t)flat[c] * W_FEAT);
        float4 f0 = __ldg(&row[lane]);
        float4 f1 = __ldg(&row[lane + 32]);
        float wc = w[c];
        acc0.x += wc * f0.x; acc0.y += wc * f0.y;
        acc0.z += wc * f0.z; acc0.w += wc * f0.w;
        acc1.x += wc * f1.x; acc1.y += wc * f1.y;
        acc1.z += wc * f1.z; acc1.w += wc * f1.w;
    }

    if (!valid) {
        acc0 = make_float4(0.f, 0.f, 0.f, 0.f);
        acc1 = make_float4(0.f, 0.f, 0.f, 0.f);
    }

    float4* fo = (float4*)(out_feat + (size_t)p * W_FEAT);
    fo[lane]      = acc0;
    fo[lane + 32] = acc1;

    if (lane == 0) {
        float s = 0.0f;
        #pragma unroll
        for (int c = 0; c < 8; c++) s += w[c] * __ldg(&grid_value[flat[c]]);
        out_val[p] = valid ? s : 0.0f;
    }
}

extern "C" void kernel_launch(void* const* d_in, const int* in_sizes, int n_in,
                              void* d_out, int out_size) {
    const float* x            = (const float*)d_in[0];
    const float* grid_value   = (const float*)d_in[1];
    const float* grid_feature = (const float*)d_in[2];

    int B = in_sizes[0] / 3;

    float* out_val  = (float*)d_out;        // (B, 1)
    float* out_feat = out_val + B;          // (B, 256)

    // --- counting sort by full cell id (lean 4-kernel pipeline) ---
    hist_kernel<<<(B + 255) / 256, 256>>>(x, B);
    scan_block_kernel<<<NCELLS / 1024, 1024>>>();
    scan_top_kernel<<<1, 256>>>();
    scatter_kernel<<<(B + 255) / 256, 256>>>(B);

    // --- main gather: warp per point, sorted order ---
    int warps_per_block = 8;                 // 256 threads
    int blocks = (B + warps_per_block - 1) / warps_per_block;
    trilerp_kernel<<<blocks, 256>>>(x, grid_value, grid_feature,
                                    out_val, out_feat, B);
}